// round 13
// baseline (speedup 1.0000x reference)
#include <cuda_runtime.h>

// Problem-size capacities (N=100000, E=1000000 in this dataset)
#define MAXN 100352
#define MAXE 1000448
#define NBLK3 592            // 148 SMs * 4, node3 grid

// ---- device scratch (static: no allocations allowed) ----
// All planes are restored to zero by their consumers each call (no memset node).
// [0,4N): layer1 accum (den,a0,a1,a2)*N ; [4N,5N): den2 ; [5N,6N): C
__device__ __align__(16) float g_zbuf[6 * MAXN];
__device__ float  g_we[MAXE];          // layer-2 edge weights (edge order)
__device__ float  g_z2[MAXN * 32];     // z2: N x 32 (30 used), coalesced rows
__device__ float  g_el2[MAXN];
__device__ float  g_er2[MAXN];
__device__ float  g_part[NBLK3 * 32];  // per-block partials
__device__ int    g_done;              // last-block counter; self-resetting

// -------- edge pass 1 (node1 folded in): per-block constants cl=W1@al1, cr=W1@ar1;
//          per edge: el1+er1 inline from feat gathers; ONE v4 RED into dst accum --------
__global__ void k_edge1(const int* __restrict__ src, const int* __restrict__ dst, int e,
                        const float* __restrict__ feat, const float* __restrict__ W1,
                        const float* __restrict__ al1, const float* __restrict__ ar1) {
    __shared__ float sc[6];   // cl0,cr0,cl1,cr1,cl2,cr2
    int t = threadIdx.x, lane = t & 31;
    if (t < 192) {
        int which = t >> 5;              // 0..5
        int j = which >> 1;              // feat dim
        const float* a = (which & 1) ? ar1 : al1;
        float p = __ldg(W1 + j * 128 + lane) * __ldg(a + lane)
                + __ldg(W1 + j * 128 + lane + 32) * __ldg(a + lane + 32);
        #pragma unroll
        for (int d = 16; d; d >>= 1) p += __shfl_down_sync(0xffffffffu, p, d);
        if (lane == 0) sc[which] = p;
    }
    __syncthreads();
    int i = blockIdx.x * blockDim.x + t;
    if (i >= e) return;
    int s = src[i], d = dst[i];
    float f0 = __ldg(feat + 3 * s), f1 = __ldg(feat + 3 * s + 1), f2 = __ldg(feat + 3 * s + 2);
    float g0 = __ldg(feat + 3 * d), g1 = __ldg(feat + 3 * d + 1), g2 = __ldg(feat + 3 * d + 2);
    float el = f0 * sc[0] + f1 * sc[2] + f2 * sc[4];
    float er = g0 * sc[1] + g1 * sc[3] + g2 * sc[5];
    float ee = el + er;
    float w = __expf(ee > 0.f ? ee : 0.2f * ee);
    float* A = g_zbuf + 4 * d;           // 16B-aligned (g_zbuf is __align__(16))
    asm volatile("red.global.add.v4.f32 [%0], {%1, %2, %3, %4};"
                 :: "l"(A), "f"(w), "f"(w * f0), "f"(w * f1), "f"(w * f2)
                 : "memory");
}

// -------- node pass 2: h1 = acc/den ; r1 = relu(h1@W1 + b1) ; z2 = r1@W2 ; el2/er2.
//          Restores its accumulator slot to zero for the next replay. --------
__global__ void k_node2(const float* __restrict__ W1, const float* __restrict__ b1,
                        const float* __restrict__ W2, const float* __restrict__ al2,
                        const float* __restrict__ ar2, int n) {
    int i = blockIdx.x * blockDim.x + threadIdx.x;
    if (i >= n) return;
    float4* Ap = (float4*)(g_zbuf + 4 * i);
    const float4 A = *Ap;
    *Ap = make_float4(0.f, 0.f, 0.f, 0.f);   // restore zero for next call
    float inv = (A.x > 0.f) ? (1.f / A.x) : 0.f;
    float h0 = A.y * inv, h1 = A.z * inv, h2 = A.w * inv;
    float z2[30];
    #pragma unroll
    for (int j = 0; j < 30; j++) z2[j] = 0.f;
    for (int k = 0; k < 64; k++) {
        float r = h0 * __ldg(W1 + k) + h1 * __ldg(W1 + 128 + k) + h2 * __ldg(W1 + 256 + k)
                + __ldg(b1 + k);
        r = fmaxf(r, 0.f);
        const float* w2row = W2 + k * 60;
        #pragma unroll
        for (int j = 0; j < 30; j++) z2[j] += r * __ldg(w2row + j);
    }
    float el2 = 0.f, er2 = 0.f;
    float* zo = g_z2 + i * 32;
    #pragma unroll
    for (int j = 0; j < 30; j++) {
        zo[j] = z2[j];
        el2 += z2[j] * __ldg(al2 + j);
        er2 += z2[j] * __ldg(ar2 + j);
    }
    zo[30] = 0.f;
    zo[31] = 0.f;
    g_el2[i] = el2;
    g_er2[i] = er2;
}

// -------- edge pass 2: w = exp(leaky(el2[s]+er2[d])) ; store w ; den2[dst] += w --------
__global__ void k_edge2(const int* __restrict__ src, const int* __restrict__ dst, int e) {
    int i = blockIdx.x * blockDim.x + threadIdx.x;
    if (i >= e) return;
    int s = src[i], d = dst[i];
    float ee = __ldg(&g_el2[s]) + __ldg(&g_er2[d]);
    float w = __expf(ee > 0.f ? ee : 0.2f * ee);
    g_we[i] = w;
    atomicAdd(g_zbuf + 4 * MAXN + d, w);
}

// -------- edge pass 3: C[src] += w / den2[dst]  (w read coalesced) --------
__global__ void k_edge3(const int* __restrict__ src, const int* __restrict__ dst, int e) {
    int i = blockIdx.x * blockDim.x + threadIdx.x;
    if (i >= e) return;
    int s = src[i], d = dst[i];
    float w = g_we[i];
    float den = __ldg(g_zbuf + 4 * MAXN + d);   // >= w > 0 since this edge contributed
    atomicAdd(g_zbuf + 5 * MAXN + s, w / den);
}

// -------- node pass 3 + final: sum_s C[s]*z2[s] (lane-locked components), then tail.
//          Each s is visited by exactly one warp (stride multiple of 32), so that warp
//          restores C[s]=0 and den2[s]=0 after reading — no memset node needed. --------
__global__ void k_node3f(int n,
                         const float* __restrict__ x, const float* __restrict__ vocab,
                         const float* __restrict__ W_lin1, const float* __restrict__ w2c,
                         const float* __restrict__ w3c, const float* __restrict__ W_lin4,
                         const float* __restrict__ b2, float* __restrict__ out) {
    __shared__ float bs[32];
    int t = threadIdx.x, lane = t & 31;
    if (t < 32) bs[t] = 0.f;
    __syncthreads();
    float* den2 = g_zbuf + 4 * MAXN;
    float* C    = g_zbuf + 5 * MAXN;
    float acc = 0.f;
    int total = n * 32;
    // stride is a multiple of 32 -> each lane keeps a fixed component j = lane,
    // and all 32 lanes of a warp share s = i >> 5
    for (int i = blockIdx.x * blockDim.x + t; i < total; i += gridDim.x * blockDim.x) {
        int s = i >> 5;
        acc += C[s] * __ldg(g_z2 + i);
        if (lane == 0) C[s] = 0.f;       // restore zero (only this warp touches s)
        if (lane == 1) den2[s] = 0.f;    // edge3 (last den2 reader) already completed
    }
    atomicAdd(&bs[lane], acc);
    __syncthreads();
    if (t < 32) g_part[blockIdx.x * 32 + t] = bs[t];
    __threadfence();
    __shared__ int amLast;
    if (t == 0) amLast = (atomicAdd(&g_done, 1) == (int)gridDim.x - 1);
    __syncthreads();
    if (!amLast) return;

    // ---------------- final phase (single block, 256 threads) ----------------
    if (t == 0) g_done = 0;                    // restore invariant for next replay
    __shared__ float s30[32];
    __shared__ float hi[32];
    __shared__ float hv[72];
    __shared__ float xs[512];
    __shared__ float lg[2];
    if (t < 32) s30[t] = 0.f;
    xs[t] = __ldg(x + t);
    xs[t + 256] = __ldg(x + t + 256);
    __syncthreads();
    {
        float acc2 = 0.f;
        int j = t & 31;
        for (int bb = t >> 5; bb < (int)gridDim.x; bb += 8) acc2 += g_part[bb * 32 + j];
        atomicAdd(&s30[j], acc2);
    }
    int w8 = t >> 5;
    #pragma unroll
    for (int it = 0; it < 4; it++) {
        int r = w8 + 8 * it;
        if (r < 30) {
            float p = 0.f;
            for (int k = lane; k < 512; k += 32) p += xs[k] * __ldg(W_lin1 + r * 512 + k);
            #pragma unroll
            for (int d = 16; d; d >>= 1) p += __shfl_down_sync(0xffffffffu, p, d);
            if (lane == 0) hi[r] = p;
        }
    }
    __syncthreads();
    if (t < 30) {
        hv[t] = s30[t] / (float)n + b2[t];     // a[0,0]
        float h = hi[t], a = 0.f;
        for (int i2 = 0; i2 < 64; i2++) {
            float s2 = 1.f / (1.f + expf(-w2c[i2] * h));
            a += w3c[i2] * s2;
        }
        hv[30 + t] = 1.f / (1.f + expf(-a));    // h_img
    }
    if (t >= 32 && t < 42) hv[60 + (t - 32)] = vocab[t - 32];
    __syncthreads();
    if (t < 2) {
        float l = 0.f;
        for (int k = 0; k < 70; k++) l += __ldg(W_lin4 + t * 70 + k) * hv[k];
        lg[t] = l;
    }
    __syncthreads();
    if (t < 2) {
        float m = fmaxf(lg[0], lg[1]);
        float lse = m + logf(expf(lg[0] - m) + expf(lg[1] - m));
        out[t] = lg[t] - lse;
    }
}

extern "C" void kernel_launch(void* const* d_in, const int* in_sizes, int n_in,
                              void* d_out, int out_size) {
    const float* x      = (const float*)d_in[0];
    const float* feat   = (const float*)d_in[1];
    const float* vocab  = (const float*)d_in[2];
    const int*   src    = (const int*)d_in[3];
    const int*   dst    = (const int*)d_in[4];
    const float* W_lin1 = (const float*)d_in[5];
    const float* w_c2   = (const float*)d_in[6];
    const float* w_c3   = (const float*)d_in[7];
    const float* W_lin4 = (const float*)d_in[8];
    const float* W1     = (const float*)d_in[9];
    const float* al1    = (const float*)d_in[10];
    const float* ar1    = (const float*)d_in[11];
    const float* b1     = (const float*)d_in[12];
    const float* W2     = (const float*)d_in[13];
    const float* al2    = (const float*)d_in[14];
    const float* ar2    = (const float*)d_in[15];
    const float* b2     = (const float*)d_in[16];

    int N = in_sizes[1] / 3;
    int E = in_sizes[3];
    int nodeBlocks = (N + 255) / 256;
    int edgeBlocks = (E + 255) / 256;

    k_edge1<<<edgeBlocks, 256>>>(src, dst, E, feat, W1, al1, ar1);
    k_node2<<<nodeBlocks, 256>>>(W1, b1, W2, al2, ar2, N);
    k_edge2<<<edgeBlocks, 256>>>(src, dst, E);
    k_edge3<<<edgeBlocks, 256>>>(src, dst, E);
    k_node3f<<<NBLK3, 256>>>(N, x, vocab, W_lin1, w_c2, w_c3, W_lin4, b2, (float*)d_out);
}

// round 17
// speedup vs baseline: 1.6254x; 1.6254x over previous
#include <cuda_runtime.h>

// Problem-size capacities (N=100000, E=1000000 in this dataset)
#define MAXN 100352
#define MAXE 1000448
#define NBLK3 592            // 148 SMs * 4, node3 grid

// ---- device scratch (static: no allocations allowed) ----
// Zero-planes are restored by their last consumer each call (no memset node).
// [0,4N): layer1 accum (den,a0,a1,a2)*N ; [4N,5N): den2 ; [5N,6N): C
__device__ __align__(16) float g_zbuf[6 * MAXN];
__device__ float4 g_f4[MAXN];          // (f0, f1, f2, el1) per node
__device__ float  g_er1[MAXN];
__device__ float  g_we[MAXE];          // layer-2 edge weights (edge order)
__device__ float  g_el2[MAXN];
__device__ float  g_er2[MAXN];
__device__ float  g_part[NBLK3 * 64];  // per-block partial SCR vectors
__device__ int    g_done;              // last-block counter; self-resetting

// -------- node pass 1: el1/er1 via collapsed 3-vectors cl = W1@al1, cr = W1@ar1 --------
__global__ void k_node1(const float* __restrict__ feat, const float* __restrict__ W1,
                        const float* __restrict__ al1, const float* __restrict__ ar1, int n) {
    __shared__ float sc[6];   // cl0,cr0,cl1,cr1,cl2,cr2
    int t = threadIdx.x, lane = t & 31;
    if (t < 192) {
        int which = t >> 5;              // 0..5
        int j = which >> 1;              // feat dim
        const float* a = (which & 1) ? ar1 : al1;
        float p = __ldg(W1 + j * 128 + lane) * __ldg(a + lane)
                + __ldg(W1 + j * 128 + lane + 32) * __ldg(a + lane + 32);
        #pragma unroll
        for (int d = 16; d; d >>= 1) p += __shfl_down_sync(0xffffffffu, p, d);
        if (lane == 0) sc[which] = p;
    }
    __syncthreads();
    int i = blockIdx.x * blockDim.x + t;
    if (i >= n) return;
    float f0 = feat[3 * i], f1 = feat[3 * i + 1], f2 = feat[3 * i + 2];
    float el = f0 * sc[0] + f1 * sc[2] + f2 * sc[4];
    float er = f0 * sc[1] + f1 * sc[3] + f2 * sc[5];
    g_f4[i] = make_float4(f0, f1, f2, el);
    g_er1[i] = er;
}

// -------- edge pass 1: {den1,acc0,acc1,acc2}[dst] += w*{1,f0,f1,f2} in ONE v4 RED --------
__global__ void k_edge1(const int* __restrict__ src, const int* __restrict__ dst, int e) {
    int i = blockIdx.x * blockDim.x + threadIdx.x;
    if (i >= e) return;
    int s = src[i], d = dst[i];
    float4 fs = __ldg(&g_f4[s]);
    float ee = fs.w + __ldg(&g_er1[d]);
    float w = __expf(ee > 0.f ? ee : 0.2f * ee);
    float* A = g_zbuf + 4 * d;           // 16B-aligned (g_zbuf is __align__(16))
    asm volatile("red.global.add.v4.f32 [%0], {%1, %2, %3, %4};"
                 :: "l"(A), "f"(w), "f"(w * fs.x), "f"(w * fs.y), "f"(w * fs.z)
                 : "memory");
}

// -------- node pass 2: h = acc/den ; r1 = relu(h@W1+b1) on the fly ;
//          el2 = r1·(W2@al2), er2 = r1·(W2@ar2). No z2 materialization. --------
__global__ void k_node2(const float* __restrict__ W1, const float* __restrict__ b1,
                        const float* __restrict__ W2, const float* __restrict__ al2,
                        const float* __restrict__ ar2, int n) {
    __shared__ float scl[64], scr[64];
    int t = threadIdx.x;
    if (t < 128) {
        int k = t & 63;
        const float* a = (t < 64) ? al2 : ar2;
        float p = 0.f;
        #pragma unroll
        for (int j = 0; j < 30; j++) p += __ldg(W2 + k * 60 + j) * __ldg(a + j);
        if (t < 64) scl[k] = p; else scr[k] = p;
    }
    __syncthreads();
    int i = blockIdx.x * blockDim.x + t;
    if (i >= n) return;
    const float4 A = *(const float4*)(g_zbuf + 4 * i);   // read only; node3f zeroes it
    float inv = (A.x > 0.f) ? (1.f / A.x) : 0.f;
    float h0 = A.y * inv, h1 = A.z * inv, h2 = A.w * inv;
    float el2 = 0.f, er2 = 0.f;
    #pragma unroll 8
    for (int k = 0; k < 64; k++) {
        float r = h0 * __ldg(W1 + k) + h1 * __ldg(W1 + 128 + k) + h2 * __ldg(W1 + 256 + k)
                + __ldg(b1 + k);
        r = fmaxf(r, 0.f);
        el2 += r * scl[k];
        er2 += r * scr[k];
    }
    g_el2[i] = el2;
    g_er2[i] = er2;
}

// -------- edge pass 2: w = exp(leaky(el2[s]+er2[d])) ; store w ; den2[dst] += w --------
__global__ void k_edge2(const int* __restrict__ src, const int* __restrict__ dst, int e) {
    int i = blockIdx.x * blockDim.x + threadIdx.x;
    if (i >= e) return;
    int s = src[i], d = dst[i];
    float ee = __ldg(&g_el2[s]) + __ldg(&g_er2[d]);
    float w = __expf(ee > 0.f ? ee : 0.2f * ee);
    g_we[i] = w;
    atomicAdd(g_zbuf + 4 * MAXN + d, w);
}

// -------- edge pass 3: C[src] += w / den2[dst]  (w read coalesced) --------
__global__ void k_edge3(const int* __restrict__ src, const int* __restrict__ dst, int e) {
    int i = blockIdx.x * blockDim.x + threadIdx.x;
    if (i >= e) return;
    int s = src[i], d = dst[i];
    float w = g_we[i];
    float den = __ldg(g_zbuf + 4 * MAXN + d);   // >= w > 0 since this edge contributed
    atomicAdd(g_zbuf + 5 * MAXN + s, w / den);
}

// -------- node pass 3 + final: SCR = sum_s C[s]*r1[s] with r1 recomputed from accum;
//          warp per node, lane-locked components k=lane, k+32. Zero-restores
//          accum/C/den2 (this kernel is their last reader). Final block applies W2. ----
__global__ void k_node3f(int n,
                         const float* __restrict__ W1, const float* __restrict__ b1,
                         const float* __restrict__ W2,
                         const float* __restrict__ x, const float* __restrict__ vocab,
                         const float* __restrict__ W_lin1, const float* __restrict__ w2c,
                         const float* __restrict__ w3c, const float* __restrict__ W_lin4,
                         const float* __restrict__ b2, float* __restrict__ out) {
    __shared__ float sW1[192];   // sW1[j*64+k] = W1[j*128+k], k<64
    __shared__ float sb1[64];
    __shared__ float sS[64];
    int t = threadIdx.x, lane = t & 31, wib = t >> 5;   // 8 warps / 256 threads
    if (t < 64) { sb1[t] = __ldg(b1 + t); sS[t] = 0.f; }
    if (t < 192) sW1[t] = __ldg(W1 + (t >> 6) * 128 + (t & 63));
    __syncthreads();
    float4* accum = (float4*)g_zbuf;
    float* den2 = g_zbuf + 4 * MAXN;
    float* C    = g_zbuf + 5 * MAXN;
    float a0 = 0.f, a1 = 0.f;
    int nwarps = gridDim.x * 8;
    for (int s = blockIdx.x * 8 + wib; s < n; s += nwarps) {
        float4 A = accum[s];                 // broadcast load (all lanes same addr)
        float Cs = C[s];
        float inv = (A.x > 0.f) ? (1.f / A.x) : 0.f;
        float h0 = A.y * inv, h1 = A.z * inv, h2 = A.w * inv;
        int k = lane;
        float r = fmaxf(h0 * sW1[k] + h1 * sW1[64 + k] + h2 * sW1[128 + k] + sb1[k], 0.f);
        a0 += Cs * r;
        k = lane + 32;
        r = fmaxf(h0 * sW1[k] + h1 * sW1[64 + k] + h2 * sW1[128 + k] + sb1[k], 0.f);
        a1 += Cs * r;
        // restore zeros for next replay (only this warp touches node s; all reads above done)
        if (lane == 0) accum[s] = make_float4(0.f, 0.f, 0.f, 0.f);
        if (lane == 1) C[s] = 0.f;
        if (lane == 2) den2[s] = 0.f;
    }
    atomicAdd(&sS[lane], a0);
    atomicAdd(&sS[lane + 32], a1);
    __syncthreads();
    if (t < 64) g_part[blockIdx.x * 64 + t] = sS[t];
    __threadfence();
    __shared__ int amLast;
    if (t == 0) amLast = (atomicAdd(&g_done, 1) == (int)gridDim.x - 1);
    __syncthreads();
    if (!amLast) return;

    // ---------------- final phase (single block, 256 threads) ----------------
    if (t == 0) g_done = 0;                    // restore invariant for next replay
    __shared__ float sS2[64];
    __shared__ float hi[32];
    __shared__ float hv[72];
    __shared__ float xs[512];
    __shared__ float lg[2];
    if (t < 64) sS2[t] = 0.f;
    xs[t] = __ldg(x + t);
    xs[t + 256] = __ldg(x + t + 256);
    __syncthreads();
    {   // reduce g_part[gridDim.x][64]
        float acc2 = 0.f;
        int k = t & 63;
        for (int bb = t >> 6; bb < (int)gridDim.x; bb += 4) acc2 += g_part[bb * 64 + k];
        atomicAdd(&sS2[k], acc2);
    }
    int w8 = t >> 5;
    #pragma unroll
    for (int it = 0; it < 4; it++) {
        int r = w8 + 8 * it;
        if (r < 30) {
            float p = 0.f;
            for (int k = lane; k < 512; k += 32) p += xs[k] * __ldg(W_lin1 + r * 512 + k);
            #pragma unroll
            for (int d = 16; d; d >>= 1) p += __shfl_down_sync(0xffffffffu, p, d);
            if (lane == 0) hi[r] = p;
        }
    }
    __syncthreads();
    if (t < 30) {
        // a[0,0][t] = (SCR @ W2[:, t]) / N + b2[t]
        float z = 0.f;
        #pragma unroll 8
        for (int k = 0; k < 64; k++) z += sS2[k] * __ldg(W2 + k * 60 + t);
        hv[t] = z / (float)n + __ldg(b2 + t);
        float h = hi[t], a = 0.f;
        for (int i2 = 0; i2 < 64; i2++) {
            float s2 = 1.f / (1.f + expf(-w2c[i2] * h));
            a += w3c[i2] * s2;
        }
        hv[30 + t] = 1.f / (1.f + expf(-a));    // h_img
    }
    if (t >= 32 && t < 42) hv[60 + (t - 32)] = vocab[t - 32];
    __syncthreads();
    if (t < 2) {
        float l = 0.f;
        for (int k = 0; k < 70; k++) l += __ldg(W_lin4 + t * 70 + k) * hv[k];
        lg[t] = l;
    }
    __syncthreads();
    if (t < 2) {
        float m = fmaxf(lg[0], lg[1]);
        float lse = m + logf(expf(lg[0] - m) + expf(lg[1] - m));
        out[t] = lg[t] - lse;
    }
}

extern "C" void kernel_launch(void* const* d_in, const int* in_sizes, int n_in,
                              void* d_out, int out_size) {
    const float* x      = (const float*)d_in[0];
    const float* feat   = (const float*)d_in[1];
    const float* vocab  = (const float*)d_in[2];
    const int*   src    = (const int*)d_in[3];
    const int*   dst    = (const int*)d_in[4];
    const float* W_lin1 = (const float*)d_in[5];
    const float* w_c2   = (const float*)d_in[6];
    const float* w_c3   = (const float*)d_in[7];
    const float* W_lin4 = (const float*)d_in[8];
    const float* W1     = (const float*)d_in[9];
    const float* al1    = (const float*)d_in[10];
    const float* ar1    = (const float*)d_in[11];
    const float* b1     = (const float*)d_in[12];
    const float* W2     = (const float*)d_in[13];
    const float* al2    = (const float*)d_in[14];
    const float* ar2    = (const float*)d_in[15];
    const float* b2     = (const float*)d_in[16];

    int N = in_sizes[1] / 3;
    int E = in_sizes[3];
    int nodeBlocks = (N + 255) / 256;
    int edgeBlocks = (E + 255) / 256;

    k_node1<<<nodeBlocks, 256>>>(feat, W1, al1, ar1, N);
    k_edge1<<<edgeBlocks, 256>>>(src, dst, E);
    k_node2<<<nodeBlocks, 256>>>(W1, b1, W2, al2, ar2, N);
    k_edge2<<<edgeBlocks, 256>>>(src, dst, E);
    k_edge3<<<edgeBlocks, 256>>>(src, dst, E);
    k_node3f<<<NBLK3, 256>>>(N, W1, b1, W2, x, vocab, W_lin1, w_c2, w_c3, W_lin4, b2,
                             (float*)d_out);
}